// round 1
// baseline (speedup 1.0000x reference)
#include <cuda_runtime.h>
#include <cstdint>

#define N_PTS      16384
#define B_SZ       4
#define S_SAMPLES  1024
#define K_NB       32
#define C_FEAT     128

#define FPS_T      512
#define PAIRS      16          // 32 points per thread, packed as 16 f32x2 pairs

#define CEN_OFF    0
#define GX_OFF     (B_SZ * S_SAMPLES * 3)                       // 12288
#define GF_OFF     (GX_OFF + B_SZ * S_SAMPLES * K_NB * 3)      // 405504

typedef unsigned long long ull;

// ---------------- packed f32x2 helpers (exact per-lane round-to-nearest) ----
__device__ __forceinline__ ull pack2(float lo, float hi) {
    ull r;
    asm("mov.b64 %0, {%1, %2};" : "=l"(r) : "f"(lo), "f"(hi));
    return r;
}
__device__ __forceinline__ void unpack2(ull v, float& lo, float& hi) {
    asm("mov.b64 {%0, %1}, %2;" : "=f"(lo), "=f"(hi) : "l"(v));
}
__device__ __forceinline__ ull addx2(ull a, ull b) {
    ull r; asm("add.rn.f32x2 %0, %1, %2;" : "=l"(r) : "l"(a), "l"(b)); return r;
}
__device__ __forceinline__ ull mulx2(ull a, ull b) {
    ull r; asm("mul.rn.f32x2 %0, %1, %2;" : "=l"(r) : "l"(a), "l"(b)); return r;
}

// ============================================================================
// Kernel A: farthest point sampling. One block per batch.
// Points register-resident (x,y,z as f32x2 pairs). Running min-dist in SMEM
// (each slot touched by exactly one thread -> no races, no fences needed).
// Argmax with jnp tie-breaking (first occurrence of max) via 64-bit key:
//   key = (float_bits(v) << 32) | (0xFFFFFFFF - idx);  max(key) == (max v, min idx)
// Distance arithmetic matches reference: rn((dx*dx + dy*dy) + dz*dz), no FMA.
// ============================================================================
extern __shared__ unsigned char sm_raw[];

__global__ __launch_bounds__(FPS_T, 1)
void fps_kernel(const float* __restrict__ xyz, float* __restrict__ out)
{
    float* s_mind = (float*)sm_raw;                      // N_PTS floats (64KB)
    ull*   s_red  = (ull*)(sm_raw + N_PTS * 4);          // 16 partials + 1 final

    const int t = threadIdx.x;
    const int b = blockIdx.x;
    const float* base = xyz + (size_t)b * N_PTS * 3;
    float* cen = out + CEN_OFF + (size_t)b * S_SAMPLES * 3;

    // Load this thread's 32 points into registers, packed as pairs.
    // Pair q holds global indices i0 = t + 1024*q and i1 = i0 + 512.
    ull X[PAIRS], Y[PAIRS], Z[PAIRS];
#pragma unroll
    for (int q = 0; q < PAIRS; ++q) {
        int i0 = t + 1024 * q, i1 = i0 + 512;
        X[q] = pack2(base[i0 * 3 + 0], base[i1 * 3 + 0]);
        Y[q] = pack2(base[i0 * 3 + 1], base[i1 * 3 + 1]);
        Z[q] = pack2(base[i0 * 3 + 2], base[i1 * 3 + 2]);
    }
    for (int i = t; i < N_PTS; i += FPS_T) s_mind[i] = 1e10f;

    // First sample is index 0 (matches reference).
    float lx = __ldg(base + 0), ly = __ldg(base + 1), lz = __ldg(base + 2);
    if (t == 0) { cen[0] = lx; cen[1] = ly; cen[2] = lz; }
    __syncthreads();

    for (int s = 1; s < S_SAMPLES; ++s) {
        const ull nx = pack2(-lx, -lx);
        const ull ny = pack2(-ly, -ly);
        const ull nz = pack2(-lz, -lz);
        float vmax = -1.0f;
        int   imax = 0;
#pragma unroll
        for (int q = 0; q < PAIRS; ++q) {
            ull dx = addx2(X[q], nx);                 // x - lx  (rn)
            ull dy = addx2(Y[q], ny);
            ull dz = addx2(Z[q], nz);
            ull d2 = addx2(addx2(mulx2(dx, dx), mulx2(dy, dy)), mulx2(dz, dz));
            float d0, d1; unpack2(d2, d0, d1);
            const int i0 = t + 1024 * q;
            float m0 = s_mind[i0];
            m0 = fminf(m0, d0);
            s_mind[i0] = m0;
            if (m0 > vmax) { vmax = m0; imax = i0; }   // strict > keeps earliest idx
            const int i1 = i0 + 512;
            float m1 = s_mind[i1];
            m1 = fminf(m1, d1);
            s_mind[i1] = m1;
            if (m1 > vmax) { vmax = m1; imax = i1; }
        }

        ull key = ((ull)__float_as_uint(vmax) << 32) | (unsigned)(0xFFFFFFFFu - (unsigned)imax);
#pragma unroll
        for (int off = 16; off > 0; off >>= 1) {
            ull o = __shfl_down_sync(0xFFFFFFFFu, key, off);
            if (o > key) key = o;
        }
        const int w = t >> 5;
        if ((t & 31) == 0) s_red[w] = key;
        __syncthreads();
        if (w == 0) {
            const int l = t & 31;
            ull k2 = (l < (FPS_T / 32)) ? s_red[l] : 0ull;
#pragma unroll
            for (int off = 8; off > 0; off >>= 1) {
                ull o = __shfl_down_sync(0xFFFFFFFFu, k2, off);
                if (o > k2) k2 = o;
            }
            if (l == 0) s_red[16] = k2;
        }
        __syncthreads();

        const ull wk = s_red[16];
        const int widx = (int)(0xFFFFFFFFu - (unsigned)wk);
        lx = __ldg(base + widx * 3 + 0);
        ly = __ldg(base + widx * 3 + 1);
        lz = __ldg(base + widx * 3 + 2);
        if (t == 0) { cen[s * 3 + 0] = lx; cen[s * 3 + 1] = ly; cen[s * 3 + 2] = lz; }
        __syncthreads();   // protects s_red reuse next iteration
    }
}

// ============================================================================
// Kernel B: ball query (first K in-radius by ascending index, pad with first
// hit) + gather of centered xyz and features. One warp per centroid, with
// early exit once K hits are found. Points scanned in j-major / lane-minor
// order == ascending global index, so ballot order == reference top_k order.
// ============================================================================
#define BQ_WARPS 8

__global__ __launch_bounds__(BQ_WARPS * 32, 4)
void group_kernel(const float* __restrict__ xyz,
                  const float* __restrict__ feat,
                  float* __restrict__ out)
{
    const int w    = threadIdx.x >> 5;
    const int lane = threadIdx.x & 31;
    const int c    = blockIdx.x * BQ_WARPS + w;          // centroid id 0..4095
    const int b    = c >> 10;
    const float* base = xyz + (size_t)b * N_PTS * 3;

    const float* cen = out + CEN_OFF + (size_t)c * 3;
    const float cx = __ldg(cen + 0), cy = __ldg(cen + 1), cz = __ldg(cen + 2);
    const float R2 = (float)(0.2 * 0.2);

    __shared__ int s_idx[BQ_WARPS][K_NB];

    int cnt = 0;
    for (int j = 0; j < N_PTS / 32 && cnt < K_NB; ++j) {
        const int p = j * 32 + lane;
        const float dx = __fadd_rn(cx, -base[p * 3 + 0]);
        const float dy = __fadd_rn(cy, -base[p * 3 + 1]);
        const float dz = __fadd_rn(cz, -base[p * 3 + 2]);
        const float sq = __fadd_rn(__fadd_rn(__fmul_rn(dx, dx), __fmul_rn(dy, dy)),
                                   __fmul_rn(dz, dz));
        const bool hit = (sq <= R2);
        const unsigned m = __ballot_sync(0xFFFFFFFFu, hit);
        if (hit) {
            const int pos = cnt + __popc(m & ((1u << lane) - 1u));
            if (pos < K_NB) s_idx[w][pos] = p;
        }
        cnt += __popc(m);
    }
    __syncwarp();
    const int first = s_idx[w][0];          // always >=1 hit (centroid itself)
    if (cnt < K_NB && lane >= cnt) s_idx[w][lane] = first;
    __syncwarp();

    // grouped_xyz (centered): one neighbor per lane
    {
        const int gi = s_idx[w][lane];
        float* go = out + GX_OFF + ((size_t)c * K_NB + lane) * 3;
        go[0] = __fadd_rn(base[gi * 3 + 0], -cx);
        go[1] = __fadd_rn(base[gi * 3 + 1], -cy);
        go[2] = __fadd_rn(base[gi * 3 + 2], -cz);
    }

    // grouped features: 32 neighbors x 128 floats, float4 per lane per row
    const float4* f4 = (const float4*)feat;
    float4* o4 = (float4*)(out + GF_OFF) + (size_t)c * K_NB * (C_FEAT / 4);
#pragma unroll 4
    for (int k = 0; k < K_NB; ++k) {
        const int gi = s_idx[w][k];
        o4[(size_t)k * (C_FEAT / 4) + lane] =
            f4[((size_t)b * N_PTS + gi) * (C_FEAT / 4) + lane];
    }
}

// ============================================================================
extern "C" void kernel_launch(void* const* d_in, const int* in_sizes, int n_in,
                              void* d_out, int out_size)
{
    const float* xyz  = (const float*)d_in[0];
    const float* feat = (const float*)d_in[1];
    if (n_in >= 2 && in_sizes[0] > in_sizes[1]) {   // defensive: xyz is smaller
        const float* tmp = xyz; xyz = feat; feat = tmp;
    }
    float* out = (float*)d_out;

    const int fps_smem = N_PTS * 4 + 32 * 8;   // min_d + reduction scratch
    cudaFuncSetAttribute(fps_kernel, cudaFuncAttributeMaxDynamicSharedMemorySize,
                         fps_smem);
    fps_kernel<<<B_SZ, FPS_T, fps_smem>>>(xyz, out);
    group_kernel<<<(B_SZ * S_SAMPLES) / BQ_WARPS, BQ_WARPS * 32>>>(xyz, feat, out);
}